// round 2
// baseline (speedup 1.0000x reference)
#include <cuda_runtime.h>
#include <cstdint>

// ---------------------------------------------------------------------------
// Problem constants
//   x  [1024,4096]  Wq [4096,16384]  bq[16384]  Wk [4096,16384]  bk[16384]
//   v  [256,4096]   Wl [4096,4096]   bl[4096]   out [1024,4096] fp32
// ---------------------------------------------------------------------------
#define B_SZ   1024
#define FIN    4096
#define NMEM   256
#define SQF    64
#define QKN    (NMEM * SQF)   // 16384

// Scratch (no allocation allowed -> __device__ globals)
__device__ float g_tmp[B_SZ * QKN];     // 64 MB: holds relu(xq) then relu(xk)
__device__ float g_qsum[B_SZ * SQF];    // 256 KB
__device__ float g_savg[B_SZ * NMEM];   // 1 MB
__device__ float g_pooled[B_SZ * FIN];  // 16 MB

// ---------------------------------------------------------------------------
// SGEMM: C = (A @ B) [+ bias] [+ res], optional relu.
// A row-major [M,K], B row-major [K,N]. 128x128 block tile, BK=8, 8x8/thread.
// Requires M%128==0, N%128==0, K%8==0 (all shapes here satisfy this).
// ---------------------------------------------------------------------------
template<bool RELU, bool BIAS, bool RES>
__global__ __launch_bounds__(256, 2)
void sgemm128(const float* __restrict__ A, const float* __restrict__ B,
              const float* __restrict__ bias, const float* __restrict__ res,
              float* __restrict__ C, int M, int N, int K)
{
    __shared__ float As[2][8][128];
    __shared__ float Bs[2][8][128];

    const int bm0 = blockIdx.y * 128;
    const int bn0 = blockIdx.x * 128;
    const int tid = threadIdx.x;
    const int tx  = tid & 15;        // 0..15  (N direction)
    const int ty  = tid >> 4;        // 0..15  (M direction)

    // A-loader: 128 rows x 8 k's = 1024 floats, float4 each
    const int arow = tid >> 1;             // 0..127
    const int acol = (tid & 1) * 4;        // 0 or 4
    // B-loader: 8 k-rows x 128 cols
    const int brow = tid >> 5;             // 0..7
    const int bcol = (tid & 31) * 4;       // 0..124

    const float* Aptr = A + (size_t)(bm0 + arow) * K + acol;
    const float* Bptr = B + (size_t)brow * N + bn0 + bcol;

    float4 a4 = *(const float4*)Aptr;
    float4 b4 = *(const float4*)Bptr;
    As[0][acol + 0][arow] = a4.x;
    As[0][acol + 1][arow] = a4.y;
    As[0][acol + 2][arow] = a4.z;
    As[0][acol + 3][arow] = a4.w;
    *(float4*)&Bs[0][brow][bcol] = b4;
    __syncthreads();

    float acc[8][8];
    #pragma unroll
    for (int i = 0; i < 8; i++)
        #pragma unroll
        for (int j = 0; j < 8; j++) acc[i][j] = 0.f;

    const int nk = K >> 3;
    for (int kt = 0; kt < nk; kt++) {
        const int buf = kt & 1;
        if (kt + 1 < nk) {
            a4 = *(const float4*)(Aptr + (size_t)(kt + 1) * 8);
            b4 = *(const float4*)(Bptr + (size_t)(kt + 1) * 8 * N);
        }
        #pragma unroll
        for (int k = 0; k < 8; k++) {
            float ra[8], rb[8];
            *(float4*)&ra[0] = *(const float4*)&As[buf][k][ty * 8];
            *(float4*)&ra[4] = *(const float4*)&As[buf][k][ty * 8 + 4];
            *(float4*)&rb[0] = *(const float4*)&Bs[buf][k][tx * 8];
            *(float4*)&rb[4] = *(const float4*)&Bs[buf][k][tx * 8 + 4];
            #pragma unroll
            for (int i = 0; i < 8; i++)
                #pragma unroll
                for (int j = 0; j < 8; j++)
                    acc[i][j] = fmaf(ra[i], rb[j], acc[i][j]);
        }
        if (kt + 1 < nk) {
            const int nb = buf ^ 1;
            As[nb][acol + 0][arow] = a4.x;
            As[nb][acol + 1][arow] = a4.y;
            As[nb][acol + 2][arow] = a4.z;
            As[nb][acol + 3][arow] = a4.w;
            *(float4*)&Bs[nb][brow][bcol] = b4;
        }
        __syncthreads();
    }

    // Epilogue
    #pragma unroll
    for (int i = 0; i < 8; i++) {
        const int row = bm0 + ty * 8 + i;
        #pragma unroll
        for (int j = 0; j < 8; j += 4) {
            const int col = bn0 + tx * 8 + j;
            float4 o;
            o.x = acc[i][j + 0];
            o.y = acc[i][j + 1];
            o.z = acc[i][j + 2];
            o.w = acc[i][j + 3];
            if (BIAS) {
                const float4 bb = *(const float4*)&bias[col];
                o.x += bb.x; o.y += bb.y; o.z += bb.z; o.w += bb.w;
            }
            if (RES) {
                const float4 rr = *(const float4*)&res[(size_t)row * N + col];
                o.x += rr.x; o.y += rr.y; o.z += rr.z; o.w += rr.w;
            }
            if (RELU) {
                o.x = fmaxf(o.x, 0.f); o.y = fmaxf(o.y, 0.f);
                o.z = fmaxf(o.z, 0.f); o.w = fmaxf(o.w, 0.f);
            }
            *(float4*)&C[(size_t)row * N + col] = o;
        }
    }
}

// ---------------------------------------------------------------------------
// q_sum[b,s] = sum_{m<256} g_tmp[b, m*64 + s]   (g_tmp holds relu(xq))
// grid=1024, block=256
// ---------------------------------------------------------------------------
__global__ void qsum_kernel()
{
    const int b = blockIdx.x;
    const int t = threadIdx.x;
    const int s = t & 63;
    const int g = t >> 6;   // 0..3
    const float* base = g_tmp + (size_t)b * QKN;
    float sum = 0.f;
    #pragma unroll 4
    for (int m = g; m < NMEM; m += 4) sum += base[m * SQF + s];
    __shared__ float sh[4][64];
    sh[g][s] = sum;
    __syncthreads();
    if (g == 0)
        g_qsum[b * SQF + s] = sh[0][s] + sh[1][s] + sh[2][s] + sh[3][s];
}

// ---------------------------------------------------------------------------
// s_avg[b,n] = (1/(256*8)) * sum_s g_tmp[b, n*64+s] * q_sum[b,s]
//  (g_tmp now holds relu(xk)). grid=1024, block=256 (8 warps, warp per n-slice)
// ---------------------------------------------------------------------------
__global__ void savg_kernel()
{
    const int b = blockIdx.x;
    const int t = threadIdx.x;
    const int lane = t & 31;
    const int w = t >> 5;   // 0..7
    __shared__ float q[64];
    if (t < 64) q[t] = g_qsum[b * SQF + t];
    __syncthreads();
    const float* base = g_tmp + (size_t)b * QKN;
    const float inv = 1.0f / (256.0f * 8.0f);
    for (int n = w; n < NMEM; n += 8) {
        float sum = base[n * SQF + lane] * q[lane]
                  + base[n * SQF + 32 + lane] * q[32 + lane];
        #pragma unroll
        for (int off = 16; off; off >>= 1)
            sum += __shfl_xor_sync(0xffffffffu, sum, off);
        if (lane == 0) g_savg[b * NMEM + n] = sum * inv;
    }
}

// ---------------------------------------------------------------------------
extern "C" void kernel_launch(void* const* d_in, const int* in_sizes, int n_in,
                              void* d_out, int out_size)
{
    const float* x  = (const float*)d_in[0];
    const float* Wq = (const float*)d_in[1];
    const float* bq = (const float*)d_in[2];
    const float* Wk = (const float*)d_in[3];
    const float* bk = (const float*)d_in[4];
    const float* v  = (const float*)d_in[5];
    const float* Wl = (const float*)d_in[6];
    const float* bl = (const float*)d_in[7];
    float* out = (float*)d_out;

    float *tmp, *savg, *pooled;
    cudaGetSymbolAddress((void**)&tmp,    g_tmp);
    cudaGetSymbolAddress((void**)&savg,   g_savg);
    cudaGetSymbolAddress((void**)&pooled, g_pooled);

    // 1) relu(x @ Wq + bq) -> tmp   [1024,16384]
    {
        dim3 grid(QKN / 128, B_SZ / 128);
        sgemm128<true, true, false><<<grid, 256>>>(x, Wq, bq, nullptr, tmp,
                                                   B_SZ, QKN, FIN);
    }
    // 2) q_sum
    qsum_kernel<<<B_SZ, 256>>>();
    // 3) relu(x @ Wk + bk) -> tmp   [1024,16384]
    {
        dim3 grid(QKN / 128, B_SZ / 128);
        sgemm128<true, true, false><<<grid, 256>>>(x, Wk, bk, nullptr, tmp,
                                                   B_SZ, QKN, FIN);
    }
    // 4) s_avg
    savg_kernel<<<B_SZ, 256>>>();
    // 5) pooled = s_avg @ v   [1024,256]@[256,4096]
    {
        dim3 grid(FIN / 128, B_SZ / 128);
        sgemm128<false, false, false><<<grid, 256>>>(savg, v, nullptr, nullptr,
                                                     pooled, B_SZ, FIN, NMEM);
    }
    // 6) out = x + pooled @ Wl + bl
    {
        dim3 grid(FIN / 128, B_SZ / 128);
        sgemm128<false, true, true><<<grid, 256>>>(pooled, Wl, bl, x, out,
                                                   B_SZ, FIN, FIN);
    }
}

// round 4
// speedup vs baseline: 1.8102x; 1.8102x over previous
#include <cuda_runtime.h>
#include <cuda_bf16.h>
#include <cstdint>

#define B_SZ   1024
#define FIN    4096
#define NMEM   256
#define SQF    64
#define QKN    16384

__device__ float g_tmp[B_SZ * QKN];
__device__ float g_qsum[B_SZ * SQF];
__device__ float g_savg[B_SZ * NMEM];
__device__ float g_pooled[B_SZ * FIN];

__device__ __forceinline__ uint32_t smem_u32(const void* p) {
    uint32_t a;
    asm("{ .reg .u64 t; cvta.to.shared.u64 t, %1; cvt.u32.u64 %0, t; }"
        : "=r"(a) : "l"(p));
    return a;
}
__device__ __forceinline__ void ldsm4(uint32_t* r, uint32_t a) {
    asm volatile("ldmatrix.sync.aligned.m8n8.x4.shared.b16 {%0,%1,%2,%3}, [%4];"
                 : "=r"(r[0]), "=r"(r[1]), "=r"(r[2]), "=r"(r[3]) : "r"(a));
}
__device__ __forceinline__ void ldsm4t(uint32_t* r, uint32_t a) {
    asm volatile("ldmatrix.sync.aligned.m8n8.x4.trans.shared.b16 {%0,%1,%2,%3}, [%4];"
                 : "=r"(r[0]), "=r"(r[1]), "=r"(r[2]), "=r"(r[3]) : "r"(a));
}
__device__ __forceinline__ void mma_bf16(float* d, const uint32_t* a, const uint32_t* b) {
    asm volatile(
        "mma.sync.aligned.m16n8k16.row.col.f32.bf16.bf16.f32 "
        "{%0,%1,%2,%3}, {%4,%5,%6,%7}, {%8,%9}, {%0,%1,%2,%3};"
        : "+f"(d[0]), "+f"(d[1]), "+f"(d[2]), "+f"(d[3])
        : "r"(a[0]), "r"(a[1]), "r"(a[2]), "r"(a[3]), "r"(b[0]), "r"(b[1]));
}
__device__ __forceinline__ void split2(float x, float y, uint32_t& hi, uint32_t& lo) {
    __nv_bfloat16 hx = __float2bfloat16(x);
    __nv_bfloat16 hy = __float2bfloat16(y);
    __nv_bfloat16 lx = __float2bfloat16(x - __bfloat162float(hx));
    __nv_bfloat16 ly = __float2bfloat16(y - __bfloat162float(hy));
    hi = (uint32_t)__bfloat16_as_ushort(hx) | ((uint32_t)__bfloat16_as_ushort(hy) << 16);
    lo = (uint32_t)__bfloat16_as_ushort(lx) | ((uint32_t)__bfloat16_as_ushort(ly) << 16);
}

// C[M,N] = A[M,K] @ B[K,N] (+bias)(+res)(relu).
// CTA tile 128x128, BK=32, 8 warps (2m x 4n), warp tile 64x32.
// bf16 split-3 (hh + h*lo + lo*h), fp32 accum.
template<bool RELU, bool BIAS, bool RES>
__global__ __launch_bounds__(256)
void tgemm(const float* __restrict__ A, const float* __restrict__ B,
           const float* __restrict__ bias, const float* __restrict__ res,
           float* __restrict__ C, int M, int N, int K)
{
    // A tiles: 128 rows x 32 k, row = 64B. B tiles: 32 k-rows x 128 n, row = 256B.
    __shared__ __align__(128) uint8_t sAh[8192];
    __shared__ __align__(128) uint8_t sAl[8192];
    __shared__ __align__(128) uint8_t sBh[8192];
    __shared__ __align__(128) uint8_t sBl[8192];

    const int tid = threadIdx.x;
    const int lane = tid & 31, wid = tid >> 5;
    const int wm = wid & 1, wn = wid >> 1;
    const int bm0 = blockIdx.x * 128, bn0 = blockIdx.y * 128;

    const uint32_t uAh = smem_u32(sAh), uAl = smem_u32(sAl);
    const uint32_t uBh = smem_u32(sBh), uBl = smem_u32(sBl);

    // loader mapping
    const int am = tid >> 1, ak = (tid & 1) * 16;   // A: 2 thr/row, 16 k each
    const int bk = tid >> 3, bn = (tid & 7) * 16;   // B: 8 thr/row, 16 n each
    const float* Ap = A + (size_t)(bm0 + am) * K + ak;
    const float* Bp = B + (size_t)bk * N + bn0 + bn;

    float4 ra[4], rb[4];
    #pragma unroll
    for (int i = 0; i < 4; i++) {
        ra[i] = *(const float4*)(Ap + 4 * i);
        rb[i] = *(const float4*)(Bp + 4 * i);
    }

    float acc[16][4];
    #pragma unroll
    for (int i = 0; i < 16; i++)
        #pragma unroll
        for (int j = 0; j < 4; j++) acc[i][j] = 0.f;

    const int NC = K >> 5;
    for (int c = 0; c < NC; c++) {
        // fill smem from regs (convert fp32 -> bf16 hi/lo)
        #pragma unroll
        for (int i = 0; i < 4; i++) {
            uint32_t h0, l0, h1, l1;
            split2(ra[i].x, ra[i].y, h0, l0);
            split2(ra[i].z, ra[i].w, h1, l1);
            uint32_t ad = (uint32_t)(am * 64 + (ak + 4 * i) * 2);
            uint32_t sw = ad ^ ((uint32_t)(am & 3) << 4);
            *(uint2*)(sAh + sw) = make_uint2(h0, h1);
            *(uint2*)(sAl + sw) = make_uint2(l0, l1);

            split2(rb[i].x, rb[i].y, h0, l0);
            split2(rb[i].z, rb[i].w, h1, l1);
            uint32_t bd = (uint32_t)(bk * 256 + (bn + 4 * i) * 2);
            uint32_t sw2 = bd ^ ((uint32_t)(bk & 7) << 4);
            *(uint2*)(sBh + sw2) = make_uint2(h0, h1);
            *(uint2*)(sBl + sw2) = make_uint2(l0, l1);
        }
        __syncthreads();

        if (c + 1 < NC) {   // prefetch next chunk (overlaps mma below)
            const float* A2 = Ap + (c + 1) * 32;
            const float* B2 = Bp + (size_t)(c + 1) * 32 * N;
            #pragma unroll
            for (int i = 0; i < 4; i++) {
                ra[i] = *(const float4*)(A2 + 4 * i);
                rb[i] = *(const float4*)(B2 + 4 * i);
            }
        }

        #pragma unroll
        for (int ks = 0; ks < 2; ks++) {
            uint32_t ah[4][4], al[4][4], bh[2][4], bl[2][4];
            #pragma unroll
            for (int mi = 0; mi < 4; mi++) {
                int row = wm * 64 + mi * 16 + (lane & 15);
                uint32_t ad = (uint32_t)(row * 64 + ks * 32 + (lane >> 4) * 16);
                uint32_t sw = ad ^ ((uint32_t)(row & 3) << 4);
                ldsm4(ah[mi], uAh + sw);
                ldsm4(al[mi], uAl + sw);
            }
            #pragma unroll
            for (int j = 0; j < 2; j++) {
                int kk = ks * 16 + (lane & 15);
                int nn = wn * 32 + j * 16 + (lane >> 4) * 8;
                uint32_t bd = (uint32_t)(kk * 256 + nn * 2);
                uint32_t sw = bd ^ ((uint32_t)(kk & 7) << 4);
                ldsm4t(bh[j], uBh + sw);
                ldsm4t(bl[j], uBl + sw);
            }
            #pragma unroll
            for (int mi = 0; mi < 4; mi++)
                #pragma unroll
                for (int nj = 0; nj < 4; nj++) {
                    const uint32_t* Bh = &bh[nj >> 1][(nj & 1) * 2];
                    const uint32_t* Bl = &bl[nj >> 1][(nj & 1) * 2];
                    float* d = acc[mi * 4 + nj];
                    mma_bf16(d, ah[mi], Bh);
                    mma_bf16(d, ah[mi], Bl);
                    mma_bf16(d, al[mi], Bh);
                }
        }
        __syncthreads();
    }

    // epilogue
    #pragma unroll
    for (int mi = 0; mi < 4; mi++) {
        const int r0 = bm0 + wm * 64 + mi * 16 + (lane >> 2);
        #pragma unroll
        for (int nj = 0; nj < 4; nj++) {
            const int col = bn0 + wn * 32 + nj * 8 + (lane & 3) * 2;
            const float* d = acc[mi * 4 + nj];
            float2 o0 = make_float2(d[0], d[1]);
            float2 o1 = make_float2(d[2], d[3]);
            if (BIAS) {
                float2 bb = *(const float2*)&bias[col];
                o0.x += bb.x; o0.y += bb.y; o1.x += bb.x; o1.y += bb.y;
            }
            if (RES) {
                float2 s0 = *(const float2*)&res[(size_t)r0 * N + col];
                float2 s1 = *(const float2*)&res[(size_t)(r0 + 8) * N + col];
                o0.x += s0.x; o0.y += s0.y; o1.x += s1.x; o1.y += s1.y;
            }
            if (RELU) {
                o0.x = fmaxf(o0.x, 0.f); o0.y = fmaxf(o0.y, 0.f);
                o1.x = fmaxf(o1.x, 0.f); o1.y = fmaxf(o1.y, 0.f);
            }
            *(float2*)&C[(size_t)r0 * N + col] = o0;
            *(float2*)&C[(size_t)(r0 + 8) * N + col] = o1;
        }
    }
}

__global__ void qsum_kernel()
{
    const int b = blockIdx.x, t = threadIdx.x;
    const int s = t & 63, g = t >> 6;
    const float* base = g_tmp + (size_t)b * QKN;
    float sum = 0.f;
    #pragma unroll 4
    for (int m = g; m < NMEM; m += 4) sum += base[m * SQF + s];
    __shared__ float sh[4][64];
    sh[g][s] = sum;
    __syncthreads();
    if (g == 0)
        g_qsum[b * SQF + s] = sh[0][s] + sh[1][s] + sh[2][s] + sh[3][s];
}

__global__ void savg_kernel()
{
    const int b = blockIdx.x, t = threadIdx.x;
    const int lane = t & 31, w = t >> 5;
    __shared__ float q[64];
    if (t < 64) q[t] = g_qsum[b * SQF + t];
    __syncthreads();
    const float* base = g_tmp + (size_t)b * QKN;
    const float inv = 1.0f / (256.0f * 8.0f);
    for (int n = w; n < NMEM; n += 8) {
        float sum = base[n * SQF + lane] * q[lane]
                  + base[n * SQF + 32 + lane] * q[32 + lane];
        #pragma unroll
        for (int off = 16; off; off >>= 1)
            sum += __shfl_xor_sync(0xffffffffu, sum, off);
        if (lane == 0) g_savg[b * NMEM + n] = sum * inv;
    }
}

extern "C" void kernel_launch(void* const* d_in, const int* in_sizes, int n_in,
                              void* d_out, int out_size)
{
    const float* x  = (const float*)d_in[0];
    const float* Wq = (const float*)d_in[1];
    const float* bq = (const float*)d_in[2];
    const float* Wk = (const float*)d_in[3];
    const float* bk = (const float*)d_in[4];
    const float* v  = (const float*)d_in[5];
    const float* Wl = (const float*)d_in[6];
    const float* bl = (const float*)d_in[7];
    float* out = (float*)d_out;

    float *tmp, *savg, *pooled;
    cudaGetSymbolAddress((void**)&tmp,    g_tmp);
    cudaGetSymbolAddress((void**)&savg,   g_savg);
    cudaGetSymbolAddress((void**)&pooled, g_pooled);

    {   // 1) relu(x@Wq+bq) -> tmp   [1024,16384]
        dim3 g(B_SZ / 128, QKN / 128);
        tgemm<true, true, false><<<g, 256>>>(x, Wq, bq, nullptr, tmp,
                                             B_SZ, QKN, FIN);
    }
    qsum_kernel<<<B_SZ, 256>>>();
    {   // 3) relu(x@Wk+bk) -> tmp
        dim3 g(B_SZ / 128, QKN / 128);
        tgemm<true, true, false><<<g, 256>>>(x, Wk, bk, nullptr, tmp,
                                             B_SZ, QKN, FIN);
    }
    savg_kernel<<<B_SZ, 256>>>();
    {   // 5) pooled = s_avg @ v   [1024,256]@[256,4096]
        dim3 g(B_SZ / 128, FIN / 128);
        tgemm<false, false, false><<<g, 256>>>(savg, v, nullptr, nullptr,
                                               pooled, B_SZ, FIN, NMEM);
    }
    {   // 6) out = x + pooled@Wl + bl
        dim3 g(B_SZ / 128, FIN / 128);
        tgemm<false, true, true><<<g, 256>>>(pooled, Wl, bl, x, out,
                                             B_SZ, FIN, FIN);
    }
}

// round 5
// speedup vs baseline: 2.2307x; 1.2323x over previous
#include <cuda_runtime.h>
#include <cuda_bf16.h>
#include <cstdint>

#define B_SZ   1024
#define FIN    4096
#define NMEM   256
#define SQF    64
#define QKN    16384

typedef __nv_bfloat16 bf16;

// fp32 scratch
__device__ float g_tmp[B_SZ * QKN];      // relu(xq) then relu(xk)
__device__ float g_qsum[B_SZ * SQF];
// bf16 hi/lo operand copies
__device__ bf16 g_xh[B_SZ * FIN],   g_xl[B_SZ * FIN];
__device__ bf16 g_wqh[FIN * QKN],   g_wql[FIN * QKN];
__device__ bf16 g_wkh[FIN * QKN],   g_wkl[FIN * QKN];
__device__ bf16 g_wlh[FIN * FIN],   g_wll[FIN * FIN];
__device__ bf16 g_vh[NMEM * FIN],   g_vl[NMEM * FIN];
__device__ bf16 g_savgh[B_SZ * NMEM], g_savgl[B_SZ * NMEM];
__device__ bf16 g_ph[B_SZ * FIN],   g_pl[B_SZ * FIN];

__device__ __forceinline__ uint32_t smem_u32(const void* p) {
    uint32_t a;
    asm("{ .reg .u64 t; cvta.to.shared.u64 t, %1; cvt.u32.u64 %0, t; }"
        : "=r"(a) : "l"(p));
    return a;
}
__device__ __forceinline__ void ldsm4(uint32_t* r, uint32_t a) {
    asm volatile("ldmatrix.sync.aligned.m8n8.x4.shared.b16 {%0,%1,%2,%3}, [%4];"
                 : "=r"(r[0]), "=r"(r[1]), "=r"(r[2]), "=r"(r[3]) : "r"(a));
}
__device__ __forceinline__ void ldsm4t(uint32_t* r, uint32_t a) {
    asm volatile("ldmatrix.sync.aligned.m8n8.x4.trans.shared.b16 {%0,%1,%2,%3}, [%4];"
                 : "=r"(r[0]), "=r"(r[1]), "=r"(r[2]), "=r"(r[3]) : "r"(a));
}
__device__ __forceinline__ void mma_bf16(float* d, const uint32_t* a, const uint32_t* b) {
    asm volatile(
        "mma.sync.aligned.m16n8k16.row.col.f32.bf16.bf16.f32 "
        "{%0,%1,%2,%3}, {%4,%5,%6,%7}, {%8,%9}, {%0,%1,%2,%3};"
        : "+f"(d[0]), "+f"(d[1]), "+f"(d[2]), "+f"(d[3])
        : "r"(a[0]), "r"(a[1]), "r"(a[2]), "r"(a[3]), "r"(b[0]), "r"(b[1]));
}
__device__ __forceinline__ void cpa16(uint32_t dst, const void* src) {
    asm volatile("cp.async.ca.shared.global [%0], [%1], 16;" :: "r"(dst), "l"(src));
}
__device__ __forceinline__ void cpa_commit() {
    asm volatile("cp.async.commit_group;" ::: "memory");
}
template<int N> __device__ __forceinline__ void cpa_wait() {
    asm volatile("cp.async.wait_group %0;" :: "n"(N) : "memory");
}
__device__ __forceinline__ void split2(float x, float y, uint32_t& hi, uint32_t& lo) {
    bf16 hx = __float2bfloat16(x);
    bf16 hy = __float2bfloat16(y);
    bf16 lx = __float2bfloat16(x - __bfloat162float(hx));
    bf16 ly = __float2bfloat16(y - __bfloat162float(hy));
    hi = (uint32_t)__bfloat16_as_ushort(hx) | ((uint32_t)__bfloat16_as_ushort(hy) << 16);
    lo = (uint32_t)__bfloat16_as_ushort(lx) | ((uint32_t)__bfloat16_as_ushort(ly) << 16);
}

// ---------------------------------------------------------------------------
// fp32 -> bf16 hi/lo conversion (grid-stride, float4)
// ---------------------------------------------------------------------------
__global__ void conv_kernel(const float4* __restrict__ in,
                            uint2* __restrict__ hi, uint2* __restrict__ lo, int n4)
{
    int i = blockIdx.x * blockDim.x + threadIdx.x;
    const int stride = gridDim.x * blockDim.x;
    for (; i < n4; i += stride) {
        float4 v = in[i];
        uint32_t h0, l0, h1, l1;
        split2(v.x, v.y, h0, l0);
        split2(v.z, v.w, h1, l1);
        hi[i] = make_uint2(h0, h1);
        lo[i] = make_uint2(l0, l1);
    }
}

// ---------------------------------------------------------------------------
// bf16 split-3 GEMM. CTA 128x128, BK=32, 3-stage cp.async pipeline.
// stage layout (32KB): Ah[0,8K) Al[8K,16K) Bh[16K,24K) Bl[24K,32K)
// ---------------------------------------------------------------------------
#define STAGE_B 32768

template<bool RELU, bool BIAS, bool RES, bool OUTBF>
__global__ __launch_bounds__(256)
void tgemm(const bf16* __restrict__ Ah, const bf16* __restrict__ Al,
           const bf16* __restrict__ Bh, const bf16* __restrict__ Bl,
           const float* __restrict__ bias, const float* __restrict__ res,
           float* __restrict__ C, bf16* __restrict__ Ch, bf16* __restrict__ Cl,
           int M, int N, int K)
{
    extern __shared__ uint8_t smem[];
    const uint32_t sb = smem_u32(smem);
    const int tid = threadIdx.x;
    const int lane = tid & 31, wid = tid >> 5;
    const int wm = wid & 1, wn = wid >> 1;
    const int bm0 = blockIdx.x * 128, bn0 = blockIdx.y * 128;

    // loader mapping
    const int arow = tid >> 1, ac = (tid & 1) * 32;   // A: 2 thr/row, 32B each
    const int brow = tid >> 3, bc = (tid & 7) * 32;   // B: 8 thr/row, 32B each
    const bf16* pAh = Ah + (size_t)(bm0 + arow) * K + ac / 2;
    const bf16* pAl = Al + (size_t)(bm0 + arow) * K + ac / 2;
    const bf16* pBh = Bh + (size_t)brow * N + bn0 + bc / 2;
    const bf16* pBl = Bl + (size_t)brow * N + bn0 + bc / 2;
    const uint32_t aswz = (uint32_t)((arow & 3) << 4);
    const uint32_t bswz = (uint32_t)((brow & 7) << 4);
    const uint32_t ao = (uint32_t)(arow * 64 + ac);
    const uint32_t bo = (uint32_t)(brow * 256 + bc);

    const int NC = K >> 5;

    auto issue = [&](int c) {
        const uint32_t u = sb + (uint32_t)(c % 3) * STAGE_B;
        const bf16* sAh = pAh + c * 32;
        const bf16* sAl = pAl + c * 32;
        const bf16* sBh = pBh + (size_t)c * 32 * N;
        const bf16* sBl = pBl + (size_t)c * 32 * N;
        cpa16(u + ((ao) ^ aswz), sAh);
        cpa16(u + ((ao + 16) ^ aswz), sAh + 8);
        cpa16(u + 8192 + ((ao) ^ aswz), sAl);
        cpa16(u + 8192 + ((ao + 16) ^ aswz), sAl + 8);
        cpa16(u + 16384 + ((bo) ^ bswz), sBh);
        cpa16(u + 16384 + ((bo + 16) ^ bswz), sBh + 8);
        cpa16(u + 24576 + ((bo) ^ bswz), sBl);
        cpa16(u + 24576 + ((bo + 16) ^ bswz), sBl + 8);
        cpa_commit();
    };

    float acc[16][4];
    #pragma unroll
    for (int i = 0; i < 16; i++)
        #pragma unroll
        for (int j = 0; j < 4; j++) acc[i][j] = 0.f;

    issue(0); issue(1); issue(2);

    for (int c = 0; c < NC; c++) {
        cpa_wait<2>();
        __syncthreads();
        const uint32_t u = sb + (uint32_t)(c % 3) * STAGE_B;
        #pragma unroll
        for (int ks = 0; ks < 2; ks++) {
            uint32_t ah[4][4], al[4][4], bh[2][4], bl[2][4];
            #pragma unroll
            for (int mi = 0; mi < 4; mi++) {
                int row = wm * 64 + mi * 16 + (lane & 15);
                uint32_t ad = (uint32_t)(row * 64 + ks * 32 + (lane >> 4) * 16);
                uint32_t sw = ad ^ ((uint32_t)(row & 3) << 4);
                ldsm4(ah[mi], u + sw);
                ldsm4(al[mi], u + 8192 + sw);
            }
            #pragma unroll
            for (int j = 0; j < 2; j++) {
                int kk = ks * 16 + (lane & 15);
                int nn = wn * 32 + j * 16 + (lane >> 4) * 8;
                uint32_t bd = (uint32_t)(kk * 256 + nn * 2);
                uint32_t sw = bd ^ ((uint32_t)(kk & 7) << 4);
                ldsm4t(bh[j], u + 16384 + sw);
                ldsm4t(bl[j], u + 24576 + sw);
            }
            #pragma unroll
            for (int mi = 0; mi < 4; mi++)
                #pragma unroll
                for (int nj = 0; nj < 4; nj++) {
                    const uint32_t* Bh2 = &bh[nj >> 1][(nj & 1) * 2];
                    const uint32_t* Bl2 = &bl[nj >> 1][(nj & 1) * 2];
                    float* d = acc[mi * 4 + nj];
                    mma_bf16(d, ah[mi], Bh2);
                    mma_bf16(d, ah[mi], Bl2);
                    mma_bf16(d, al[mi], Bh2);
                }
        }
        __syncthreads();
        if (c + 3 < NC) issue(c + 3);
    }

    // epilogue
    #pragma unroll
    for (int mi = 0; mi < 4; mi++) {
        const int r0 = bm0 + wm * 64 + mi * 16 + (lane >> 2);
        #pragma unroll
        for (int nj = 0; nj < 4; nj++) {
            const int col = bn0 + wn * 32 + nj * 8 + (lane & 3) * 2;
            float* d = acc[mi * 4 + nj];
            if (OUTBF) {
                #pragma unroll
                for (int h = 0; h < 2; h++) {
                    const int rr = r0 + 8 * h;
                    uint32_t hi, lo;
                    split2(d[2 * h], d[2 * h + 1], hi, lo);
                    *(uint32_t*)&Ch[(size_t)rr * N + col] = hi;
                    *(uint32_t*)&Cl[(size_t)rr * N + col] = lo;
                }
            } else {
                float2 o0 = make_float2(d[0], d[1]);
                float2 o1 = make_float2(d[2], d[3]);
                if (BIAS) {
                    float2 bb = *(const float2*)&bias[col];
                    o0.x += bb.x; o0.y += bb.y; o1.x += bb.x; o1.y += bb.y;
                }
                if (RES) {
                    float2 s0 = *(const float2*)&res[(size_t)r0 * N + col];
                    float2 s1 = *(const float2*)&res[(size_t)(r0 + 8) * N + col];
                    o0.x += s0.x; o0.y += s0.y; o1.x += s1.x; o1.y += s1.y;
                }
                if (RELU) {
                    o0.x = fmaxf(o0.x, 0.f); o0.y = fmaxf(o0.y, 0.f);
                    o1.x = fmaxf(o1.x, 0.f); o1.y = fmaxf(o1.y, 0.f);
                }
                *(float2*)&C[(size_t)r0 * N + col] = o0;
                *(float2*)&C[(size_t)(r0 + 8) * N + col] = o1;
            }
        }
    }
}

__global__ void qsum_kernel()
{
    const int b = blockIdx.x, t = threadIdx.x;
    const int s = t & 63, g = t >> 6;
    const float* base = g_tmp + (size_t)b * QKN;
    float sum = 0.f;
    #pragma unroll 4
    for (int m = g; m < NMEM; m += 4) sum += base[m * SQF + s];
    __shared__ float sh[4][64];
    sh[g][s] = sum;
    __syncthreads();
    if (g == 0)
        g_qsum[b * SQF + s] = sh[0][s] + sh[1][s] + sh[2][s] + sh[3][s];
}

__global__ void savg_kernel()
{
    const int b = blockIdx.x, t = threadIdx.x;
    const int lane = t & 31, w = t >> 5;
    __shared__ float q[64];
    if (t < 64) q[t] = g_qsum[b * SQF + t];
    __syncthreads();
    const float* base = g_tmp + (size_t)b * QKN;
    const float inv = 1.0f / (256.0f * 8.0f);
    for (int n = w; n < NMEM; n += 8) {
        float sum = base[n * SQF + lane] * q[lane]
                  + base[n * SQF + 32 + lane] * q[32 + lane];
        #pragma unroll
        for (int off = 16; off; off >>= 1)
            sum += __shfl_xor_sync(0xffffffffu, sum, off);
        if (lane == 0) {
            float val = sum * inv;
            bf16 h = __float2bfloat16(val);
            bf16 l = __float2bfloat16(val - __bfloat162float(h));
            g_savgh[b * NMEM + n] = h;
            g_savgl[b * NMEM + n] = l;
        }
    }
}

extern "C" void kernel_launch(void* const* d_in, const int* in_sizes, int n_in,
                              void* d_out, int out_size)
{
    const float* x  = (const float*)d_in[0];
    const float* Wq = (const float*)d_in[1];
    const float* bq = (const float*)d_in[2];
    const float* Wk = (const float*)d_in[3];
    const float* bk = (const float*)d_in[4];
    const float* v  = (const float*)d_in[5];
    const float* Wl = (const float*)d_in[6];
    const float* bl = (const float*)d_in[7];
    float* out = (float*)d_out;

    float* tmp;
    cudaGetSymbolAddress((void**)&tmp, g_tmp);
    bf16 *xh,*xl,*wqh,*wql,*wkh,*wkl,*wlh,*wll,*vh,*vl,*sh,*sl,*ph,*pl;
    cudaGetSymbolAddress((void**)&xh, g_xh);   cudaGetSymbolAddress((void**)&xl, g_xl);
    cudaGetSymbolAddress((void**)&wqh, g_wqh); cudaGetSymbolAddress((void**)&wql, g_wql);
    cudaGetSymbolAddress((void**)&wkh, g_wkh); cudaGetSymbolAddress((void**)&wkl, g_wkl);
    cudaGetSymbolAddress((void**)&wlh, g_wlh); cudaGetSymbolAddress((void**)&wll, g_wll);
    cudaGetSymbolAddress((void**)&vh, g_vh);   cudaGetSymbolAddress((void**)&vl, g_vl);
    cudaGetSymbolAddress((void**)&sh, g_savgh);cudaGetSymbolAddress((void**)&sl, g_savgl);
    cudaGetSymbolAddress((void**)&ph, g_ph);   cudaGetSymbolAddress((void**)&pl, g_pl);

    // conversions
    conv_kernel<<<1024, 256>>>((const float4*)x,  (uint2*)xh,  (uint2*)xl,  B_SZ * FIN / 4);
    conv_kernel<<<4096, 256>>>((const float4*)Wq, (uint2*)wqh, (uint2*)wql, FIN * QKN / 4);
    conv_kernel<<<4096, 256>>>((const float4*)Wk, (uint2*)wkh, (uint2*)wkl, FIN * QKN / 4);
    conv_kernel<<<2048, 256>>>((const float4*)Wl, (uint2*)wlh, (uint2*)wll, FIN * FIN / 4);
    conv_kernel<<<512,  256>>>((const float4*)v,  (uint2*)vh,  (uint2*)vl,  NMEM * FIN / 4);

    const int SM = 3 * STAGE_B;
    cudaFuncSetAttribute(tgemm<true, true, false, false>,
                         cudaFuncAttributeMaxDynamicSharedMemorySize, SM);
    cudaFuncSetAttribute(tgemm<false, false, false, true>,
                         cudaFuncAttributeMaxDynamicSharedMemorySize, SM);
    cudaFuncSetAttribute(tgemm<false, true, true, false>,
                         cudaFuncAttributeMaxDynamicSharedMemorySize, SM);

    {   // 1) relu(x@Wq+bq) -> tmp
        dim3 g(B_SZ / 128, QKN / 128);
        tgemm<true, true, false, false><<<g, 256, SM>>>(
            xh, xl, wqh, wql, bq, nullptr, tmp, nullptr, nullptr, B_SZ, QKN, FIN);
    }
    qsum_kernel<<<B_SZ, 256>>>();
    {   // 2) relu(x@Wk+bk) -> tmp
        dim3 g(B_SZ / 128, QKN / 128);
        tgemm<true, true, false, false><<<g, 256, SM>>>(
            xh, xl, wkh, wkl, bk, nullptr, tmp, nullptr, nullptr, B_SZ, QKN, FIN);
    }
    savg_kernel<<<B_SZ, 256>>>();
    {   // 3) pooled = s_avg @ v  (bf16 hi/lo out)
        dim3 g(B_SZ / 128, FIN / 128);
        tgemm<false, false, false, true><<<g, 256, SM>>>(
            sh, sl, vh, vl, nullptr, nullptr, nullptr, ph, pl, B_SZ, FIN, NMEM);
    }
    {   // 4) out = x + pooled@Wl + bl
        dim3 g(B_SZ / 128, FIN / 128);
        tgemm<false, true, true, false><<<g, 256, SM>>>(
            ph, pl, wlh, wll, bl, x, out, nullptr, nullptr, B_SZ, FIN, FIN);
    }
}